// round 14
// baseline (speedup 1.0000x reference)
#include <cuda_runtime.h>
#include <cuda_fp16.h>
#include <math.h>
#include <stdint.h>

// ---------------------------------------------------------------------------
// ShiftedWindowAttention (B=32, 64x64, C=256, 8 heads x 32, ws=8, shift=4)
//
// K0: x (gathered+rolled) -> fp16; w_qkv + w_out -> fp16; build bias+mask
//     lookup table g_tbl[wtype][head][64][64] fp16 (4 window types).
// K1: qkv GEMM -> g_q (scale folded) / g_k / g_v, head-blocked fp16
// K2: per-(window,head) attention, HMMA, register softmax; bias+mask via
//     one smem table lookup per element (replaces index-math ALU).
// K3: out = att2 @ w_out^T + b_out, inverse-roll scatter, f32
// ---------------------------------------------------------------------------

#define KDIM 256
typedef __half fp16;

#define HPLANE 4194304UL   // 131072 * 32 elements per head plane

__device__ fp16  g_x2  [131072UL * 256];   // x gathered, fp16
__device__ fp16  g_q   [131072UL * 256];   // [head][row][32], scale folded
__device__ fp16  g_k   [131072UL * 256];   // [head][row][32]
__device__ fp16  g_v   [131072UL * 256];   // [head][row][32]
__device__ fp16  g_att2[131072UL * 256];   // attention out, row-major [row][256]
__device__ fp16  g_w2  [768 * 256];        // w_qkv
__device__ fp16  g_w3  [256 * 256];        // w_out
__device__ fp16  g_tbl [4 * 8 * 4096];     // [wtype][head][i][j] bias(+mask)

static __device__ __constant__ float SCALEF = 0.17677669529663687f;  // 32^-0.5

__device__ __forceinline__ int gather_off(int gm) {
    int w  = gm >> 6;
    int t  = gm & 63;
    int b  = w >> 6;
    int wl = w & 63;
    int r  = ((wl >> 3) << 3) + (t >> 3);
    int c  = ((wl & 7) << 3) + (t & 7);
    int sr = (r + 4) & 63;
    int sc = (c + 4) & 63;
    return (b * 4096 + sr * 64 + sc) * KDIM;
}

#define SWZ(off) ((off) ^ (((off) >> 3) & 0x70))

__device__ __forceinline__ uint32_t smem_u32(const void* p) {
    uint32_t a;
    asm("{ .reg .u64 t; cvta.to.shared.u64 t, %1; cvt.u32.u64 %0, t; }"
        : "=r"(a) : "l"(p));
    return a;
}

#define LDSM4(r, addr)                                                         \
    asm volatile("ldmatrix.sync.aligned.m8n8.x4.shared.b16 {%0,%1,%2,%3}, [%4];"\
                 : "=r"((r)[0]), "=r"((r)[1]), "=r"((r)[2]), "=r"((r)[3])      \
                 : "r"(addr))

#define MMA16816(d, a, b)                                                      \
    asm volatile("mma.sync.aligned.m16n8k16.row.col.f32.f16.f16.f32 "          \
                 "{%0,%1,%2,%3}, {%4,%5,%6,%7}, {%8,%9}, {%0,%1,%2,%3};"       \
                 : "+f"((d)[0]), "+f"((d)[1]), "+f"((d)[2]), "+f"((d)[3])      \
                 : "r"((a)[0]), "r"((a)[1]), "r"((a)[2]), "r"((a)[3]),         \
                   "r"((b)[0]), "r"((b)[1]))

__device__ __forceinline__ uint32_t packh(float lo, float hi) {
    __half2 h = __floats2half2_rn(lo, hi);
    return *(uint32_t*)&h;
}

// ---------------------------------------------------------------------------
// K0a: x (gathered) -> g_x2 fp16
// ---------------------------------------------------------------------------
__global__ void convert_x(const float* __restrict__ src)
{
    int idx = blockIdx.x * blockDim.x + threadIdx.x;
    int row = idx >> 6;
    int c   = (idx & 63) << 2;
    float4 v = *(const float4*)(src + gather_off(row) + c);

    fp16 __align__(8) hi[4];
    hi[0] = __float2half_rn(v.x);
    hi[1] = __float2half_rn(v.y);
    hi[2] = __float2half_rn(v.z);
    hi[3] = __float2half_rn(v.w);
    *(uint2*)(g_x2 + (size_t)row * 256 + c) = *(uint2*)hi;
}

// K0b: both weight matrices -> fp16 in one launch
__global__ void convert_w(const float* __restrict__ wq, const float* __restrict__ wo)
{
    int idx = blockIdx.x * blockDim.x + threadIdx.x;   // 1024*64
    int row = idx >> 6;
    int c   = (idx & 63) << 2;
    const float* sp;
    fp16* dst;
    if (row < 768) { sp = wq + row * 256 + c;        dst = g_w2 + (size_t)row * 256 + c; }
    else           { sp = wo + (row - 768) * 256 + c; dst = g_w3 + (size_t)(row - 768) * 256 + c; }
    float4 v = *(const float4*)sp;
    fp16 __align__(8) hi[4];
    hi[0] = __float2half_rn(v.x);
    hi[1] = __float2half_rn(v.y);
    hi[2] = __float2half_rn(v.z);
    hi[3] = __float2half_rn(v.w);
    *(uint2*)dst = *(uint2*)hi;
}

// K0c: build combined bias+mask table per (wtype, head).
// wtype: bit0 = window in last column (cols 56..63), bit1 = last row.
__global__ void build_tbl(const float* __restrict__ pos_enc)
{
    int idx = blockIdx.x * blockDim.x + threadIdx.x;   // 131072
    int j  = idx & 63;
    int i  = (idx >> 6) & 63;
    int h  = (idx >> 12) & 7;
    int wt = idx >> 15;
    int yi = i >> 3, xi = i & 7, yj = j >> 3, xj = j & 7;
    int ri = ((wt & 2) ? ((yi < 4) ? 1 : 2) : 0) * 3
           + ((wt & 1) ? ((xi < 4) ? 1 : 2) : 0);
    int rj = ((wt & 2) ? ((yj < 4) ? 1 : 2) : 0) * 3
           + ((wt & 1) ? ((xj < 4) ? 1 : 2) : 0);
    float v = (ri != rj) ? -30000.0f
            : pos_enc[h * 225 + (yi - yj + 7) * 15 + (xi - xj + 7)];
    g_tbl[idx] = __float2half_rn(v);
}

// ---------------------------------------------------------------------------
// mma.sync GEMM.  C[128 x 128] per CTA, 8 warps, warp tile 64x32.
// K = 256 = 4 chunks of 64 cols, 2-stage cp.async pipeline.
// !SCATTER: epilogue writes head-blocked fp16 planes g_q (scaled)/g_k/g_v.
// SCATTER:  f32 output, inverse-roll row scatter (A = g_att2 row-major).
// ---------------------------------------------------------------------------
template <int NT, bool SCATTER>
__global__ __launch_bounds__(256, 2) void mma_gemm(const float* __restrict__ bias,
                                                   float* __restrict__ Cout)
{
    extern __shared__ __align__(1024) char smem[];
    const fp16* Ag = SCATTER ? g_att2 : g_x2;
    const fp16* Bg = SCATTER ? g_w3   : g_w2;

    const int tid  = threadIdx.x;
    const int lane = tid & 31;
    const int warp = tid >> 5;
    const int m0   = blockIdx.y * 128;
    const int n0c  = blockIdx.x * 128;
    const uint32_t sbase = smem_u32(smem);

    auto stage = [&](int c, int buf) {
        int kin = c * 64;
        uint32_t ab = sbase + buf * 32768;
        uint32_t bb = ab + 16384;
        #pragma unroll
        for (int i = 0; i < 4; i++) {
            int idx = tid + i * 256;
            int r  = idx >> 3;
            int ch = idx & 7;
            uint32_t off = (uint32_t)(r * 128 + ch * 16);
            const fp16* as = Ag + (size_t)(m0 + r) * 256 + kin + ch * 8;
            const fp16* bs = Bg + (size_t)(n0c + r) * 256 + kin + ch * 8;
            asm volatile("cp.async.cg.shared.global [%0], [%1], 16;"
                         :: "r"(ab + SWZ(off)), "l"(as));
            asm volatile("cp.async.cg.shared.global [%0], [%1], 16;"
                         :: "r"(bb + SWZ(off)), "l"(bs));
        }
        asm volatile("cp.async.commit_group;");
    };

    float d[4][4][4];
    #pragma unroll
    for (int mt = 0; mt < 4; mt++)
        #pragma unroll
        for (int nt = 0; nt < 4; nt++)
            #pragma unroll
            for (int j = 0; j < 4; j++) d[mt][nt][j] = 0.f;

    const int wm0 = (warp >> 2) * 64;
    const int wn0 = (warp & 3) * 32;

    stage(0, 0);
    #pragma unroll 1
    for (int c = 0; c < 4; c++) {
        if (c < 3) {
            stage(c + 1, (c + 1) & 1);
            asm volatile("cp.async.wait_group 1;");
        } else {
            asm volatile("cp.async.wait_group 0;");
        }
        __syncthreads();

        uint32_t ab = sbase + (c & 1) * 32768;
        uint32_t bb = ab + 16384;

        #pragma unroll
        for (int ks = 0; ks < 4; ks++) {
            uint32_t a[4][4], b[4][2];
            #pragma unroll
            for (int mt = 0; mt < 4; mt++) {
                int row = wm0 + mt * 16 + (lane & 15);
                int col = ks * 16 + ((lane >> 1) & 8);
                uint32_t off = (uint32_t)(row * 128 + col * 2);
                LDSM4(a[mt], ab + SWZ(off));
            }
            #pragma unroll
            for (int np = 0; np < 2; np++) {
                int row = wn0 + np * 16 + (lane & 7) + ((lane & 16) ? 8 : 0);
                int col = ks * 16 + ((lane & 8) ? 8 : 0);
                uint32_t off = (uint32_t)(row * 128 + col * 2);
                uint32_t t[4];
                LDSM4(t, bb + SWZ(off));
                b[2 * np][0] = t[0]; b[2 * np][1] = t[1];
                b[2 * np + 1][0] = t[2]; b[2 * np + 1][1] = t[3];
            }
            #pragma unroll
            for (int mt = 0; mt < 4; mt++)
                #pragma unroll
                for (int nt = 0; nt < 4; nt++)
                    MMA16816(d[mt][nt], a[mt], b[nt]);
        }
        if (c < 3) __syncthreads();
    }

    const int cc0 = n0c + wn0 + (lane & 3) * 2;
    if (SCATTER) {
        #pragma unroll
        for (int mt = 0; mt < 4; mt++) {
            int g0 = m0 + wm0 + mt * 16 + (lane >> 2);
            size_t ob0 = (size_t)gather_off(g0);
            size_t ob1 = (size_t)gather_off(g0 + 8);
            #pragma unroll
            for (int nt = 0; nt < 4; nt++) {
                int col = cc0 + nt * 8;
                float bx = bias[col], by = bias[col + 1];
                float2 o0 = {d[mt][nt][0] + bx, d[mt][nt][1] + by};
                float2 o1 = {d[mt][nt][2] + bx, d[mt][nt][3] + by};
                *(float2*)(Cout + ob0 + col) = o0;
                *(float2*)(Cout + ob1 + col) = o1;
            }
        }
    } else {
        fp16* dst   = (n0c < 256) ? g_q : ((n0c < 512) ? g_k : g_v);
        int   cbase = (n0c < 256) ? 0   : ((n0c < 512) ? 256 : 512);
        const float scl = (n0c < 256) ? SCALEF : 1.0f;
        #pragma unroll
        for (int mt = 0; mt < 4; mt++) {
            int g0 = m0 + wm0 + mt * 16 + (lane >> 2);
            #pragma unroll
            for (int nt = 0; nt < 4; nt++) {
                int col = cc0 + nt * 8;
                float bx = bias[col], by = bias[col + 1];
                float v0 = (d[mt][nt][0] + bx) * scl, v1 = (d[mt][nt][1] + by) * scl;
                float v2 = (d[mt][nt][2] + bx) * scl, v3 = (d[mt][nt][3] + by) * scl;
                int cc  = col - cbase;        // 0..255
                size_t hb = (size_t)(cc >> 5) * HPLANE + (cc & 31);
                *(uint32_t*)(dst + hb + (size_t)g0 * 32)       = packh(v0, v1);
                *(uint32_t*)(dst + hb + (size_t)(g0 + 8) * 32) = packh(v2, v3);
            }
        }
    }
}

// ---------------------------------------------------------------------------
// K2: tensor-core windowed attention; bias+mask via smem table (72-half
// padded rows -> conflict-free half2 loads).  One block per (window, head).
// ---------------------------------------------------------------------------
__global__ __launch_bounds__(128) void attn_kernel()
{
    __shared__ fp16 qh[64 * 40];
    __shared__ fp16 kh[64 * 40];
    __shared__ fp16 vh[32 * 72];               // transposed [dim][col]
    __shared__ fp16 tbl[64 * 72];              // bias+mask, padded rows

    const int w    = blockIdx.x;
    const int h    = blockIdx.y;
    const int tid  = threadIdx.x;
    const int lane = tid & 31;
    const int wp   = tid >> 5;

    const size_t hb = (size_t)h * HPLANE + (size_t)(w * 64) * 32;
    const int wl = w & 63;
    const int wtype = (((wl >> 3) == 7) ? 2 : 0) + (((wl & 7) == 7) ? 1 : 0);
    const fp16* tsrc = g_tbl + (size_t)(wtype * 8 + h) * 4096;

    for (int t = tid; t < 256; t += 128) {
        int i = t >> 2, d0 = (t & 3) * 8;
        *(uint4*)(qh + i * 40 + d0) = *(const uint4*)(g_q + hb + i * 32 + d0);
    }
    for (int t = tid; t < 256; t += 128) {
        int i = t >> 2, d0 = (t & 3) * 8;
        *(uint4*)(kh + i * 40 + d0) = *(const uint4*)(g_k + hb + i * 32 + d0);
    }
    for (int t = tid; t < 256; t += 128) {
        int i = t >> 2, d0 = (t & 3) * 8;
        fp16 tmp[8];
        *(uint4*)tmp = *(const uint4*)(g_v + hb + i * 32 + d0);
        #pragma unroll
        for (int e = 0; e < 8; e++) vh[(d0 + e) * 72 + i] = tmp[e];
    }
    for (int t = tid; t < 512; t += 128) {
        int row = t >> 3, seg = (t & 7) * 8;
        *(uint4*)(tbl + row * 72 + seg) = *(const uint4*)(tsrc + row * 64 + seg);
    }
    __syncthreads();

    const uint32_t uqh = smem_u32(qh);
    const uint32_t ukh = smem_u32(kh);
    const uint32_t uvh = smem_u32(vh);

    // ---- S = q k^T ----
    float c[8][4];
    #pragma unroll
    for (int j = 0; j < 8; j++)
        #pragma unroll
        for (int q = 0; q < 4; q++) c[j][q] = 0.f;

    uint32_t aq[2][4];
    #pragma unroll
    for (int ks = 0; ks < 2; ks++) {
        uint32_t off = (uint32_t)((wp * 16 + (lane & 15)) * 80 +
                                  (ks * 16 + ((lane >> 1) & 8)) * 2);
        LDSM4(aq[ks], uqh + off);
    }
    #pragma unroll
    for (int np = 0; np < 4; np++) {
        #pragma unroll
        for (int ks = 0; ks < 2; ks++) {
            uint32_t off = (uint32_t)((np * 16 + (lane & 7) + ((lane & 16) ? 8 : 0)) * 80 +
                                      (ks * 16 + ((lane & 8) ? 8 : 0)) * 2);
            uint32_t bh[4];
            LDSM4(bh, ukh + off);
            MMA16816(c[2 * np],     aq[ks], &bh[0]);
            MMA16816(c[2 * np + 1], aq[ks], &bh[2]);
        }
    }

    // ---- bias+mask (table) + softmax on fragments ----
    const int r0 = wp * 16 + (lane >> 2);
    const int r1 = r0 + 8;
    const fp16* t0 = tbl + r0 * 72 + (lane & 3) * 2;
    const fp16* t1 = tbl + r1 * 72 + (lane & 3) * 2;

    float mx0 = -INFINITY, mx1 = -INFINITY;
    #pragma unroll
    for (int j = 0; j < 8; j++) {
        float2 f0 = __half22float2(*(const __half2*)(t0 + j * 8));
        float2 f1 = __half22float2(*(const __half2*)(t1 + j * 8));
        c[j][0] += f0.x;  c[j][1] += f0.y;
        c[j][2] += f1.x;  c[j][3] += f1.y;
        mx0 = fmaxf(mx0, fmaxf(c[j][0], c[j][1]));
        mx1 = fmaxf(mx1, fmaxf(c[j][2], c[j][3]));
    }
    mx0 = fmaxf(mx0, __shfl_xor_sync(0xffffffffu, mx0, 1));
    mx0 = fmaxf(mx0, __shfl_xor_sync(0xffffffffu, mx0, 2));
    mx1 = fmaxf(mx1, __shfl_xor_sync(0xffffffffu, mx1, 1));
    mx1 = fmaxf(mx1, __shfl_xor_sync(0xffffffffu, mx1, 2));
    float s0 = 0.f, s1 = 0.f;
    #pragma unroll
    for (int j = 0; j < 8; j++) {
        c[j][0] = __expf(c[j][0] - mx0);  s0 += c[j][0];
        c[j][1] = __expf(c[j][1] - mx0);  s0 += c[j][1];
        c[j][2] = __expf(c[j][2] - mx1);  s1 += c[j][2];
        c[j][3] = __expf(c[j][3] - mx1);  s1 += c[j][3];
    }
    s0 += __shfl_xor_sync(0xffffffffu, s0, 1);
    s0 += __shfl_xor_sync(0xffffffffu, s0, 2);
    s1 += __shfl_xor_sync(0xffffffffu, s1, 1);
    s1 += __shfl_xor_sync(0xffffffffu, s1, 2);
    const float inv0 = 1.0f / s0, inv1 = 1.0f / s1;

    // ---- repack P (C-frag -> A-frag), single fp16 ----
    uint32_t ph[4][4];
    #pragma unroll
    for (int t = 0; t < 4; t++) {
        #pragma unroll
        for (int q = 0; q < 4; q++) {
            int nt = 2 * t + (q >> 1);
            int p0 = (q & 1) * 2;
            float iv = (p0 == 0) ? inv0 : inv1;
            ph[t][q] = packh(c[nt][p0] * iv, c[nt][p0 + 1] * iv);
        }
    }

    // ---- O = P v ----
    float o[4][4];
    #pragma unroll
    for (int nt = 0; nt < 4; nt++)
        #pragma unroll
        for (int q = 0; q < 4; q++) o[nt][q] = 0.f;

    #pragma unroll
    for (int t = 0; t < 4; t++) {
        #pragma unroll
        for (int nb = 0; nb < 2; nb++) {
            uint32_t off = (uint32_t)((nb * 16 + (lane & 7) + ((lane & 16) ? 8 : 0)) * 144 +
                                      (t * 16 + ((lane & 8) ? 8 : 0)) * 2);
            uint32_t bh[4];
            LDSM4(bh, uvh + off);
            MMA16816(o[2 * nb],     ph[t], &bh[0]);
            MMA16816(o[2 * nb + 1], ph[t], &bh[2]);
        }
    }

    // ---- epilogue: fp16 to g_att2 (row-major [row][256]) ----
    size_t rb0 = (size_t)(w * 64 + r0) * 256 + h * 32;
    size_t rb1 = (size_t)(w * 64 + r1) * 256 + h * 32;
    #pragma unroll
    for (int nt = 0; nt < 4; nt++) {
        int d0 = nt * 8 + (lane & 3) * 2;
        *(uint32_t*)(g_att2 + rb0 + d0) = packh(o[nt][0], o[nt][1]);
        *(uint32_t*)(g_att2 + rb1 + d0) = packh(o[nt][2], o[nt][3]);
    }
}

// ---------------------------------------------------------------------------
extern "C" void kernel_launch(void* const* d_in, const int* in_sizes, int n_in,
                              void* d_out, int out_size)
{
    const float* x     = (const float*)d_in[0];
    const float* w_qkv = (const float*)d_in[1];
    const float* b_qkv = (const float*)d_in[2];
    const float* w_out = (const float*)d_in[3];
    const float* b_out = (const float*)d_in[4];
    const float* pos   = (const float*)d_in[5];
    float* out = (float*)d_out;

    const int SMEM = 65536;
    cudaFuncSetAttribute(mma_gemm<6, false>,
                         cudaFuncAttributeMaxDynamicSharedMemorySize, SMEM);
    cudaFuncSetAttribute(mma_gemm<2, true>,
                         cudaFuncAttributeMaxDynamicSharedMemorySize, SMEM);

    convert_x<<<32768, 256>>>(x);
    convert_w<<<256, 256>>>(w_qkv, w_out);
    build_tbl<<<512, 256>>>(pos);
    mma_gemm<6, false><<<dim3(6, 1024), 256, SMEM>>>(b_qkv, nullptr);
    attn_kernel<<<dim3(2048, 8), 128>>>();
    mma_gemm<2, true><<<dim3(2, 1024), 256, SMEM>>>(b_out, out);
}

// round 15
// speedup vs baseline: 1.0720x; 1.0720x over previous
#include <cuda_runtime.h>
#include <cuda_fp16.h>
#include <math.h>
#include <stdint.h>

// ---------------------------------------------------------------------------
// ShiftedWindowAttention (B=32, 64x64, C=256, 8 heads x 32, ws=8, shift=4)
//
// K0: w_qkv + w_out -> fp16 (one tiny kernel)
// K1: single-pass-A qkv GEMM: CTA loads its gathered 128x256 A tile from f32
//     x ONCE (LDG+cvt+STS), then loops 6 n-tiles streaming B via cp.async.
//     Epilogue writes head-blocked fp16 planes g_q (scale folded)/g_k/g_v.
// K2: per-(window,head) attention, HMMA, register softmax (R13 version).
// K3: out = att2 @ w_out^T + b_out, inverse-roll scatter, f32.
// ---------------------------------------------------------------------------

#define KDIM 256
typedef __half fp16;

#define HPLANE 4194304UL   // 131072 * 32 elements per head plane

__device__ fp16  g_q   [131072UL * 256];   // [head][row][32], scale folded
__device__ fp16  g_k   [131072UL * 256];   // [head][row][32]
__device__ fp16  g_v   [131072UL * 256];   // [head][row][32]
__device__ fp16  g_att2[131072UL * 256];   // attention out, row-major [row][256]
__device__ fp16  g_w2  [768 * 256];        // w_qkv
__device__ fp16  g_w3  [256 * 256];        // w_out

static __device__ __constant__ float SCALEF = 0.17677669529663687f;  // 32^-0.5

__device__ __forceinline__ int gather_off(int gm) {
    int w  = gm >> 6;
    int t  = gm & 63;
    int b  = w >> 6;
    int wl = w & 63;
    int r  = ((wl >> 3) << 3) + (t >> 3);
    int c  = ((wl & 7) << 3) + (t & 7);
    int sr = (r + 4) & 63;
    int sc = (c + 4) & 63;
    return (b * 4096 + sr * 64 + sc) * KDIM;
}

#define SWZ(off) ((off) ^ (((off) >> 3) & 0x70))

__device__ __forceinline__ uint32_t smem_u32(const void* p) {
    uint32_t a;
    asm("{ .reg .u64 t; cvta.to.shared.u64 t, %1; cvt.u32.u64 %0, t; }"
        : "=r"(a) : "l"(p));
    return a;
}

#define LDSM4(r, addr)                                                         \
    asm volatile("ldmatrix.sync.aligned.m8n8.x4.shared.b16 {%0,%1,%2,%3}, [%4];"\
                 : "=r"((r)[0]), "=r"((r)[1]), "=r"((r)[2]), "=r"((r)[3])      \
                 : "r"(addr))

#define MMA16816(d, a, b)                                                      \
    asm volatile("mma.sync.aligned.m16n8k16.row.col.f32.f16.f16.f32 "          \
                 "{%0,%1,%2,%3}, {%4,%5,%6,%7}, {%8,%9}, {%0,%1,%2,%3};"       \
                 : "+f"((d)[0]), "+f"((d)[1]), "+f"((d)[2]), "+f"((d)[3])      \
                 : "r"((a)[0]), "r"((a)[1]), "r"((a)[2]), "r"((a)[3]),         \
                   "r"((b)[0]), "r"((b)[1]))

__device__ __forceinline__ uint32_t packh(float lo, float hi) {
    __half2 h = __floats2half2_rn(lo, hi);
    return *(uint32_t*)&h;
}

// ---------------------------------------------------------------------------
// K0: both weight matrices -> fp16 in one launch
// ---------------------------------------------------------------------------
__global__ void convert_w(const float* __restrict__ wq, const float* __restrict__ wo)
{
    int idx = blockIdx.x * blockDim.x + threadIdx.x;   // 1024*64
    int row = idx >> 6;
    int c   = (idx & 63) << 2;
    const float* sp;
    fp16* dst;
    if (row < 768) { sp = wq + row * 256 + c;        dst = g_w2 + (size_t)row * 256 + c; }
    else           { sp = wo + (row - 768) * 256 + c; dst = g_w3 + (size_t)(row - 768) * 256 + c; }
    float4 v = *(const float4*)sp;
    fp16 __align__(8) hi[4];
    hi[0] = __float2half_rn(v.x);
    hi[1] = __float2half_rn(v.y);
    hi[2] = __float2half_rn(v.z);
    hi[3] = __float2half_rn(v.w);
    *(uint2*)dst = *(uint2*)hi;
}

// ---------------------------------------------------------------------------
// K1: single-pass-A qkv GEMM.  grid = 1024 m-tiles; 8 warps, warp tile 64x32.
// A: 128x256 fp16 resident in smem as 4 chunk-blocks of 16KB (SW128),
//    loaded ONCE from f32 x with the roll+window gather fused in.
// B: 24 global chunks (6 n-tiles x 4 k-chunks of 64 cols), 2-stage cp.async.
// smem: A 65536 | B 2x16384  = 98304 B;  2 CTAs/SM.
// ---------------------------------------------------------------------------
__global__ __launch_bounds__(256, 2) void qkv_gemm(const float* __restrict__ X,
                                                   const float* __restrict__ bias)
{
    extern __shared__ __align__(1024) char smem[];

    const int tid  = threadIdx.x;
    const int lane = tid & 31;
    const int warp = tid >> 5;
    const int m0   = blockIdx.x * 128;
    const uint32_t sbase = smem_u32(smem);
    const uint32_t bbase = sbase + 65536;

    // ---- load A tile once: f32 gather -> fp16 smem (4 chunk-blocks) ----
    {
        const int q4 = (tid & 63) * 4;          // fixed column (f32 quad)
        const int r0 = tid >> 6;                // row stepper base
        const int kc = q4 >> 6;                 // chunk block 0..3
        char* blk = smem + kc * 16384;
        #pragma unroll
        for (int it = 0; it < 32; it++) {
            int r = r0 + it * 4;                // 0..127
            float4 v = *(const float4*)(X + gather_off(m0 + r) + q4);
            fp16 __align__(8) h[4];
            h[0] = __float2half_rn(v.x);
            h[1] = __float2half_rn(v.y);
            h[2] = __float2half_rn(v.z);
            h[3] = __float2half_rn(v.w);
            uint32_t off = (uint32_t)(r * 128 + (q4 & 63) * 2);
            *(uint2*)(blk + SWZ(off)) = *(uint2*)h;
        }
    }

    // ---- B staging: chunk gc (0..23): nt = gc>>2, kin = (gc&3)*64 ----
    auto stageB = [&](int gc, int buf) {
        int nt  = gc >> 2;
        int kin = (gc & 3) * 64;
        uint32_t bb = bbase + buf * 16384;
        #pragma unroll
        for (int i = 0; i < 4; i++) {
            int idx = tid + i * 256;
            int r  = idx >> 3;
            int ch = idx & 7;
            uint32_t off = (uint32_t)(r * 128 + ch * 16);
            const fp16* bs = g_w2 + (size_t)(nt * 128 + r) * 256 + kin + ch * 8;
            asm volatile("cp.async.cg.shared.global [%0], [%1], 16;"
                         :: "r"(bb + SWZ(off)), "l"(bs));
        }
        asm volatile("cp.async.commit_group;");
    };

    float d[4][4][4];
    #pragma unroll
    for (int mt = 0; mt < 4; mt++)
        #pragma unroll
        for (int nt = 0; nt < 4; nt++)
            #pragma unroll
            for (int j = 0; j < 4; j++) d[mt][nt][j] = 0.f;

    const int wm0 = (warp >> 2) * 64;
    const int wn0 = (warp & 3) * 32;

    stageB(0, 0);
    #pragma unroll 1
    for (int gc = 0; gc < 24; gc++) {
        const int c  = gc & 3;
        const int nt = gc >> 2;
        if (gc < 23) {
            stageB(gc + 1, (gc + 1) & 1);
            asm volatile("cp.async.wait_group 1;");
        } else {
            asm volatile("cp.async.wait_group 0;");
        }
        __syncthreads();

        uint32_t ab = sbase + c * 16384;
        uint32_t bb = bbase + (gc & 1) * 16384;

        #pragma unroll
        for (int ks = 0; ks < 4; ks++) {
            uint32_t a[4][4], b[4][2];
            #pragma unroll
            for (int mt = 0; mt < 4; mt++) {
                int row = wm0 + mt * 16 + (lane & 15);
                int col = ks * 16 + ((lane >> 1) & 8);
                uint32_t off = (uint32_t)(row * 128 + col * 2);
                LDSM4(a[mt], ab + SWZ(off));
            }
            #pragma unroll
            for (int np = 0; np < 2; np++) {
                int row = wn0 + np * 16 + (lane & 7) + ((lane & 16) ? 8 : 0);
                int col = ks * 16 + ((lane & 8) ? 8 : 0);
                uint32_t off = (uint32_t)(row * 128 + col * 2);
                uint32_t t[4];
                LDSM4(t, bb + SWZ(off));
                b[2 * np][0] = t[0]; b[2 * np][1] = t[1];
                b[2 * np + 1][0] = t[2]; b[2 * np + 1][1] = t[3];
            }
            #pragma unroll
            for (int mt = 0; mt < 4; mt++)
                #pragma unroll
                for (int n2 = 0; n2 < 4; n2++)
                    MMA16816(d[mt][n2], a[mt], b[n2]);
        }

        if (c == 3) {
            // ---- epilogue for n-tile nt: head-blocked fp16 q/k/v ----
            const int n0c = nt * 128;
            const int cc0 = n0c + wn0 + (lane & 3) * 2;
            fp16* dst   = (n0c < 256) ? g_q : ((n0c < 512) ? g_k : g_v);
            int   cbase = (n0c < 256) ? 0   : ((n0c < 512) ? 256 : 512);
            const float scl = (n0c < 256) ? SCALEF : 1.0f;
            #pragma unroll
            for (int mt = 0; mt < 4; mt++) {
                int g0 = m0 + wm0 + mt * 16 + (lane >> 2);
                #pragma unroll
                for (int n2 = 0; n2 < 4; n2++) {
                    int col = cc0 + n2 * 8;
                    float bx = bias[col], by = bias[col + 1];
                    float v0 = (d[mt][n2][0] + bx) * scl, v1 = (d[mt][n2][1] + by) * scl;
                    float v2 = (d[mt][n2][2] + bx) * scl, v3 = (d[mt][n2][3] + by) * scl;
                    int cc  = col - cbase;        // 0..255
                    size_t hb = (size_t)(cc >> 5) * HPLANE + (cc & 31);
                    *(uint32_t*)(dst + hb + (size_t)g0 * 32)       = packh(v0, v1);
                    *(uint32_t*)(dst + hb + (size_t)(g0 + 8) * 32) = packh(v2, v3);
                    d[mt][n2][0] = 0.f; d[mt][n2][1] = 0.f;
                    d[mt][n2][2] = 0.f; d[mt][n2][3] = 0.f;
                }
            }
        }
        if (gc < 23) __syncthreads();
    }
}

// ---------------------------------------------------------------------------
// K2: tensor-core windowed attention (R13 version), single fp16 everywhere.
// One block per (window, head), 4 warps, warp = 16 query rows.
// Head-blocked qkv: per CTA three contiguous 4KB reads.
// ---------------------------------------------------------------------------
__global__ __launch_bounds__(128) void attn_kernel(const float* __restrict__ pos_enc)
{
    __shared__ fp16 qh[64 * 40];
    __shared__ fp16 kh[64 * 40];
    __shared__ fp16 vh[32 * 72];               // transposed [dim][col]
    __shared__ float pe[225];
    __shared__ int   rg[64];

    const int w    = blockIdx.x;
    const int h    = blockIdx.y;
    const int tid  = threadIdx.x;
    const int lane = tid & 31;
    const int wp   = tid >> 5;

    const size_t hb = (size_t)h * HPLANE + (size_t)(w * 64) * 32;

    for (int t = tid; t < 256; t += 128) {
        int i = t >> 2, d0 = (t & 3) * 8;
        *(uint4*)(qh + i * 40 + d0) = *(const uint4*)(g_q + hb + i * 32 + d0);
    }
    for (int t = tid; t < 256; t += 128) {
        int i = t >> 2, d0 = (t & 3) * 8;
        *(uint4*)(kh + i * 40 + d0) = *(const uint4*)(g_k + hb + i * 32 + d0);
    }
    for (int t = tid; t < 256; t += 128) {
        int i = t >> 2, d0 = (t & 3) * 8;
        fp16 tmp[8];
        *(uint4*)tmp = *(const uint4*)(g_v + hb + i * 32 + d0);
        #pragma unroll
        for (int e = 0; e < 8; e++) vh[(d0 + e) * 72 + i] = tmp[e];
    }
    for (int idx = tid; idx < 225; idx += 128) pe[idx] = pos_enc[h * 225 + idx];
    if (tid < 64) {
        int wl = w & 63;
        int r  = ((wl >> 3) << 3) + (tid >> 3);
        int c  = ((wl & 7) << 3) + (tid & 7);
        int rr = (r < 56) ? 0 : ((r < 60) ? 1 : 2);
        int cc = (c < 56) ? 0 : ((c < 60) ? 1 : 2);
        rg[tid] = rr * 3 + cc;
    }
    __syncthreads();

    const uint32_t uqh = smem_u32(qh);
    const uint32_t ukh = smem_u32(kh);
    const uint32_t uvh = smem_u32(vh);

    // ---- S = q k^T ----
    float c[8][4];
    #pragma unroll
    for (int j = 0; j < 8; j++)
        #pragma unroll
        for (int q = 0; q < 4; q++) c[j][q] = 0.f;

    uint32_t aq[2][4];
    #pragma unroll
    for (int ks = 0; ks < 2; ks++) {
        uint32_t off = (uint32_t)((wp * 16 + (lane & 15)) * 80 +
                                  (ks * 16 + ((lane >> 1) & 8)) * 2);
        LDSM4(aq[ks], uqh + off);
    }
    #pragma unroll
    for (int np = 0; np < 4; np++) {
        #pragma unroll
        for (int ks = 0; ks < 2; ks++) {
            uint32_t off = (uint32_t)((np * 16 + (lane & 7) + ((lane & 16) ? 8 : 0)) * 80 +
                                      (ks * 16 + ((lane & 8) ? 8 : 0)) * 2);
            uint32_t bh[4];
            LDSM4(bh, ukh + off);
            MMA16816(c[2 * np],     aq[ks], &bh[0]);
            MMA16816(c[2 * np + 1], aq[ks], &bh[2]);
        }
    }

    // ---- bias + mask + softmax on fragments ----
    const int r0 = wp * 16 + (lane >> 2);
    const int r1 = r0 + 8;
    const int yi0 = r0 >> 3, xi0 = r0 & 7, ri0 = rg[r0];
    const int yi1 = r1 >> 3, xi1 = r1 & 7, ri1 = rg[r1];
    float mx0 = -INFINITY, mx1 = -INFINITY;
    #pragma unroll
    for (int j = 0; j < 8; j++) {
        #pragma unroll
        for (int dd = 0; dd < 2; dd++) {
            int col = j * 8 + (lane & 3) * 2 + dd;
            int yj = col >> 3, xj = col & 7;
            int rc = rg[col];
            c[j][dd]     = (rc == ri0)
                ? c[j][dd]     + pe[(yi0 - yj + 7) * 15 + (xi0 - xj + 7)] : -INFINITY;
            c[j][dd + 2] = (rc == ri1)
                ? c[j][dd + 2] + pe[(yi1 - yj + 7) * 15 + (xi1 - xj + 7)] : -INFINITY;
            mx0 = fmaxf(mx0, c[j][dd]);
            mx1 = fmaxf(mx1, c[j][dd + 2]);
        }
    }
    mx0 = fmaxf(mx0, __shfl_xor_sync(0xffffffffu, mx0, 1));
    mx0 = fmaxf(mx0, __shfl_xor_sync(0xffffffffu, mx0, 2));
    mx1 = fmaxf(mx1, __shfl_xor_sync(0xffffffffu, mx1, 1));
    mx1 = fmaxf(mx1, __shfl_xor_sync(0xffffffffu, mx1, 2));
    float s0 = 0.f, s1 = 0.f;
    #pragma unroll
    for (int j = 0; j < 8; j++) {
        #pragma unroll
        for (int dd = 0; dd < 2; dd++) {
            c[j][dd]     = __expf(c[j][dd] - mx0);     s0 += c[j][dd];
            c[j][dd + 2] = __expf(c[j][dd + 2] - mx1); s1 += c[j][dd + 2];
        }
    }
    s0 += __shfl_xor_sync(0xffffffffu, s0, 1);
    s0 += __shfl_xor_sync(0xffffffffu, s0, 2);
    s1 += __shfl_xor_sync(0xffffffffu, s1, 1);
    s1 += __shfl_xor_sync(0xffffffffu, s1, 2);
    const float inv0 = 1.0f / s0, inv1 = 1.0f / s1;

    // ---- repack P (C-frag -> A-frag), single fp16 ----
    uint32_t ph[4][4];
    #pragma unroll
    for (int t = 0; t < 4; t++) {
        #pragma unroll
        for (int q = 0; q < 4; q++) {
            int nt = 2 * t + (q >> 1);
            int p0 = (q & 1) * 2;
            float iv = (p0 == 0) ? inv0 : inv1;
            ph[t][q] = packh(c[nt][p0] * iv, c[nt][p0 + 1] * iv);
        }
    }

    // ---- O = P v ----
    float o[4][4];
    #pragma unroll
    for (int nt = 0; nt < 4; nt++)
        #pragma unroll
        for (int q = 0; q < 4; q++) o[nt][q] = 0.f;

    #pragma unroll
    for (int t = 0; t < 4; t++) {
        #pragma unroll
        for (int nb = 0; nb < 2; nb++) {
            uint32_t off = (uint32_t)((nb * 16 + (lane & 7) + ((lane & 16) ? 8 : 0)) * 144 +
                                      (t * 16 + ((lane & 8) ? 8 : 0)) * 2);
            uint32_t bh[4];
            LDSM4(bh, uvh + off);
            MMA16816(o[2 * nb],     ph[t], &bh[0]);
            MMA16816(o[2 * nb + 1], ph[t], &bh[2]);
        }
    }

    // ---- epilogue: fp16 to g_att2 (row-major [row][256]) ----
    size_t rb0 = (size_t)(w * 64 + r0) * 256 + h * 32;
    size_t rb1 = (size_t)(w * 64 + r1) * 256 + h * 32;
    #pragma unroll
    for (int nt = 0; nt < 4; nt++) {
        int d0 = nt * 8 + (lane & 3) * 2;
        *(uint32_t*)(g_att2 + rb0 + d0) = packh(o[nt][0], o[nt][1]);
        *(uint32_t*)(g_att2 + rb1 + d0) = packh(o[nt][2], o[nt][3]);
    }
}

// ---------------------------------------------------------------------------
// K3: out-projection GEMM + inverse-roll scatter (unchanged from R13).
// ---------------------------------------------------------------------------
__global__ __launch_bounds__(256, 2) void out_gemm(const float* __restrict__ bias,
                                                   float* __restrict__ Cout)
{
    extern __shared__ __align__(1024) char smem[];

    const int tid  = threadIdx.x;
    const int lane = tid & 31;
    const int warp = tid >> 5;
    const int m0   = blockIdx.y * 128;
    const int n0c  = blockIdx.x * 128;
    const uint32_t sbase = smem_u32(smem);

    auto stage = [&](int c, int buf) {
        int kin = c * 64;
        uint32_t ab = sbase + buf * 32768;
        uint32_t bb = ab + 16384;
        #pragma unroll
        for (int i = 0; i < 4; i++) {
            int idx = tid + i * 256;
            int r  = idx >> 3;
            int ch = idx & 7;
            uint32_t off = (uint32_t)(r * 128 + ch * 16);
            const fp16* as = g_att2 + (size_t)(m0 + r) * 256 + kin + ch * 8;
            const fp16* bs = g_w3 + (size_t)(n0c + r) * 256 + kin + ch * 8;
            asm volatile("cp.async.cg.shared.global [%0], [%1], 16;"
                         :: "r"(ab + SWZ(off)), "l"(as));
            asm volatile("cp.async.cg.shared.global [%0], [%1], 16;"
                         :: "r"(bb + SWZ(off)), "l"(bs));
        }
        asm volatile("cp.async.commit_group;");
    };

    float d[4][4][4];
    #pragma unroll
    for (int mt = 0; mt < 4; mt++)
        #pragma unroll
        for (int nt = 0; nt < 4; nt++)
            #pragma unroll
            for (int j = 0; j < 4; j++) d[mt][nt][j] = 0.f;

    const int wm0 = (warp >> 2) * 64;
    const int wn0 = (warp & 3) * 32;

    stage(0, 0);
    #pragma unroll 1
    for (int c = 0; c < 4; c++) {
        if (c < 3) {
            stage(c + 1, (c + 1) & 1);
            asm volatile("cp.async.wait_group 1;");
        } else {
            asm volatile("cp.async.wait_group 0;");
        }
        __syncthreads();

        uint32_t ab = sbase + (c & 1) * 32768;
        uint32_t bb = ab + 16384;

        #pragma unroll
        for (int ks = 0; ks < 4; ks++) {
            uint32_t a[4][4], b[4][2];
            #pragma unroll
            for (int mt = 0; mt < 4; mt++) {
                int row = wm0 + mt * 16 + (lane & 15);
                int col = ks * 16 + ((lane >> 1) & 8);
                uint32_t off = (uint32_t)(row * 128 + col * 2);
                LDSM4(a[mt], ab + SWZ(off));
            }
            #pragma unroll
            for (int np = 0; np < 2; np++) {
                int row = wn0 + np * 16 + (lane & 7) + ((lane & 16) ? 8 : 0);
                int col = ks * 16 + ((lane & 8) ? 8 : 0);
                uint32_t off = (uint32_t)(row * 128 + col * 2);
                uint32_t t[4];
                LDSM4(t, bb + SWZ(off));
                b[2 * np][0] = t[0]; b[2 * np][1] = t[1];
                b[2 * np + 1][0] = t[2]; b[2 * np + 1][1] = t[3];
            }
            #pragma unroll
            for (int mt = 0; mt < 4; mt++)
                #pragma unroll
                for (int nt = 0; nt < 4; nt++)
                    MMA16816(d[mt][nt], a[mt], b[nt]);
        }
        if (c < 3) __syncthreads();
    }

    const int cc0 = n0c + wn0 + (lane & 3) * 2;
    #pragma unroll
    for (int mt = 0; mt < 4; mt++) {
        int g0 = m0 + wm0 + mt * 16 + (lane >> 2);
        size_t ob0 = (size_t)gather_off(g0);
        size_t ob1 = (size_t)gather_off(g0 + 8);
        #pragma unroll
        for (int nt = 0; nt < 4; nt++) {
            int col = cc0 + nt * 8;
            float bx = bias[col], by = bias[col + 1];
            float2 o0 = {d[mt][nt][0] + bx, d[mt][nt][1] + by};
            float2 o1 = {d[mt][nt][2] + bx, d[mt][nt][3] + by};
            *(float2*)(Cout + ob0 + col) = o0;
            *(float2*)(Cout + ob1 + col) = o1;
        }
    }
}

// ---------------------------------------------------------------------------
extern "C" void kernel_launch(void* const* d_in, const int* in_sizes, int n_in,
                              void* d_out, int out_size)
{
    const float* x     = (const float*)d_in[0];
    const float* w_qkv = (const float*)d_in[1];
    const float* b_qkv = (const float*)d_in[2];
    const float* w_out = (const float*)d_in[3];
    const float* b_out = (const float*)d_in[4];
    const float* pos   = (const float*)d_in[5];
    float* out = (float*)d_out;

    const int SMEM1 = 98304;   // qkv_gemm: A 64KB + B 2x16KB
    const int SMEM3 = 65536;   // out_gemm
    cudaFuncSetAttribute(qkv_gemm,
                         cudaFuncAttributeMaxDynamicSharedMemorySize, SMEM1);
    cudaFuncSetAttribute(out_gemm,
                         cudaFuncAttributeMaxDynamicSharedMemorySize, SMEM3);

    convert_w<<<256, 256>>>(w_qkv, w_out);
    qkv_gemm<<<1024, 256, SMEM1>>>(x, b_qkv);
    attn_kernel<<<dim3(2048, 8), 128>>>(pos);
    out_gemm<<<dim3(2, 1024), 256, SMEM3>>>(b_out, out);
}

// round 16
// speedup vs baseline: 1.0737x; 1.0016x over previous
#include <cuda_runtime.h>
#include <cuda_fp16.h>
#include <math.h>
#include <stdint.h>

// ---------------------------------------------------------------------------
// ShiftedWindowAttention (B=32, 64x64, C=256, 8 heads x 32, ws=8, shift=4)
//
// K0: w_qkv + w_out -> fp16 (one tiny kernel)
// K1: single-pass-A qkv GEMM: CTA loads its gathered 128x256 A tile from f32
//     x ONCE (LDG+cvt+STS), then loops 6 n-tiles streaming B via cp.async.
//     Epilogue writes head-blocked fp16 planes g_q (scale folded)/g_k/g_v.
// K2: per-(window,head) attention, HMMA, register softmax.
// K3: single-pass-A out GEMM: A tile (g_att2) staged once, 2 n-tiles of
//     w_out streamed; bias + inverse-roll scatter, f32.
// ---------------------------------------------------------------------------

#define KDIM 256
typedef __half fp16;

#define HPLANE 4194304UL   // 131072 * 32 elements per head plane

__device__ fp16  g_q   [131072UL * 256];   // [head][row][32], scale folded
__device__ fp16  g_k   [131072UL * 256];   // [head][row][32]
__device__ fp16  g_v   [131072UL * 256];   // [head][row][32]
__device__ fp16  g_att2[131072UL * 256];   // attention out, row-major [row][256]
__device__ fp16  g_w2  [768 * 256];        // w_qkv
__device__ fp16  g_w3  [256 * 256];        // w_out

static __device__ __constant__ float SCALEF = 0.17677669529663687f;  // 32^-0.5

__device__ __forceinline__ int gather_off(int gm) {
    int w  = gm >> 6;
    int t  = gm & 63;
    int b  = w >> 6;
    int wl = w & 63;
    int r  = ((wl >> 3) << 3) + (t >> 3);
    int c  = ((wl & 7) << 3) + (t & 7);
    int sr = (r + 4) & 63;
    int sc = (c + 4) & 63;
    return (b * 4096 + sr * 64 + sc) * KDIM;
}

#define SWZ(off) ((off) ^ (((off) >> 3) & 0x70))

__device__ __forceinline__ uint32_t smem_u32(const void* p) {
    uint32_t a;
    asm("{ .reg .u64 t; cvta.to.shared.u64 t, %1; cvt.u32.u64 %0, t; }"
        : "=r"(a) : "l"(p));
    return a;
}

#define LDSM4(r, addr)                                                         \
    asm volatile("ldmatrix.sync.aligned.m8n8.x4.shared.b16 {%0,%1,%2,%3}, [%4];"\
                 : "=r"((r)[0]), "=r"((r)[1]), "=r"((r)[2]), "=r"((r)[3])      \
                 : "r"(addr))

#define MMA16816(d, a, b)                                                      \
    asm volatile("mma.sync.aligned.m16n8k16.row.col.f32.f16.f16.f32 "          \
                 "{%0,%1,%2,%3}, {%4,%5,%6,%7}, {%8,%9}, {%0,%1,%2,%3};"       \
                 : "+f"((d)[0]), "+f"((d)[1]), "+f"((d)[2]), "+f"((d)[3])      \
                 : "r"((a)[0]), "r"((a)[1]), "r"((a)[2]), "r"((a)[3]),         \
                   "r"((b)[0]), "r"((b)[1]))

__device__ __forceinline__ uint32_t packh(float lo, float hi) {
    __half2 h = __floats2half2_rn(lo, hi);
    return *(uint32_t*)&h;
}

// ---------------------------------------------------------------------------
// K0: both weight matrices -> fp16 in one launch
// ---------------------------------------------------------------------------
__global__ void convert_w(const float* __restrict__ wq, const float* __restrict__ wo)
{
    int idx = blockIdx.x * blockDim.x + threadIdx.x;   // 1024*64
    int row = idx >> 6;
    int c   = (idx & 63) << 2;
    const float* sp;
    fp16* dst;
    if (row < 768) { sp = wq + row * 256 + c;        dst = g_w2 + (size_t)row * 256 + c; }
    else           { sp = wo + (row - 768) * 256 + c; dst = g_w3 + (size_t)(row - 768) * 256 + c; }
    float4 v = *(const float4*)sp;
    fp16 __align__(8) hi[4];
    hi[0] = __float2half_rn(v.x);
    hi[1] = __float2half_rn(v.y);
    hi[2] = __float2half_rn(v.z);
    hi[3] = __float2half_rn(v.w);
    *(uint2*)dst = *(uint2*)hi;
}

// ---------------------------------------------------------------------------
// K1: single-pass-A qkv GEMM.  grid = 1024 m-tiles; 8 warps, warp tile 64x32.
// ---------------------------------------------------------------------------
__global__ __launch_bounds__(256, 2) void qkv_gemm(const float* __restrict__ X,
                                                   const float* __restrict__ bias)
{
    extern __shared__ __align__(1024) char smem[];

    const int tid  = threadIdx.x;
    const int lane = tid & 31;
    const int warp = tid >> 5;
    const int m0   = blockIdx.x * 128;
    const uint32_t sbase = smem_u32(smem);
    const uint32_t bbase = sbase + 65536;

    // ---- load A tile once: f32 gather -> fp16 smem (4 chunk-blocks) ----
    {
        const int q4 = (tid & 63) * 4;
        const int r0 = tid >> 6;
        const int kc = q4 >> 6;
        char* blk = smem + kc * 16384;
        #pragma unroll
        for (int it = 0; it < 32; it++) {
            int r = r0 + it * 4;
            float4 v = *(const float4*)(X + gather_off(m0 + r) + q4);
            fp16 __align__(8) h[4];
            h[0] = __float2half_rn(v.x);
            h[1] = __float2half_rn(v.y);
            h[2] = __float2half_rn(v.z);
            h[3] = __float2half_rn(v.w);
            uint32_t off = (uint32_t)(r * 128 + (q4 & 63) * 2);
            *(uint2*)(blk + SWZ(off)) = *(uint2*)h;
        }
    }

    auto stageB = [&](int gc, int buf) {
        int nt  = gc >> 2;
        int kin = (gc & 3) * 64;
        uint32_t bb = bbase + buf * 16384;
        #pragma unroll
        for (int i = 0; i < 4; i++) {
            int idx = tid + i * 256;
            int r  = idx >> 3;
            int ch = idx & 7;
            uint32_t off = (uint32_t)(r * 128 + ch * 16);
            const fp16* bs = g_w2 + (size_t)(nt * 128 + r) * 256 + kin + ch * 8;
            asm volatile("cp.async.cg.shared.global [%0], [%1], 16;"
                         :: "r"(bb + SWZ(off)), "l"(bs));
        }
        asm volatile("cp.async.commit_group;");
    };

    float d[4][4][4];
    #pragma unroll
    for (int mt = 0; mt < 4; mt++)
        #pragma unroll
        for (int nt = 0; nt < 4; nt++)
            #pragma unroll
            for (int j = 0; j < 4; j++) d[mt][nt][j] = 0.f;

    const int wm0 = (warp >> 2) * 64;
    const int wn0 = (warp & 3) * 32;

    stageB(0, 0);
    #pragma unroll 1
    for (int gc = 0; gc < 24; gc++) {
        const int c  = gc & 3;
        const int nt = gc >> 2;
        if (gc < 23) {
            stageB(gc + 1, (gc + 1) & 1);
            asm volatile("cp.async.wait_group 1;");
        } else {
            asm volatile("cp.async.wait_group 0;");
        }
        __syncthreads();

        uint32_t ab = sbase + c * 16384;
        uint32_t bb = bbase + (gc & 1) * 16384;

        #pragma unroll
        for (int ks = 0; ks < 4; ks++) {
            uint32_t a[4][4], b[4][2];
            #pragma unroll
            for (int mt = 0; mt < 4; mt++) {
                int row = wm0 + mt * 16 + (lane & 15);
                int col = ks * 16 + ((lane >> 1) & 8);
                uint32_t off = (uint32_t)(row * 128 + col * 2);
                LDSM4(a[mt], ab + SWZ(off));
            }
            #pragma unroll
            for (int np = 0; np < 2; np++) {
                int row = wn0 + np * 16 + (lane & 7) + ((lane & 16) ? 8 : 0);
                int col = ks * 16 + ((lane & 8) ? 8 : 0);
                uint32_t off = (uint32_t)(row * 128 + col * 2);
                uint32_t t[4];
                LDSM4(t, bb + SWZ(off));
                b[2 * np][0] = t[0]; b[2 * np][1] = t[1];
                b[2 * np + 1][0] = t[2]; b[2 * np + 1][1] = t[3];
            }
            #pragma unroll
            for (int mt = 0; mt < 4; mt++)
                #pragma unroll
                for (int n2 = 0; n2 < 4; n2++)
                    MMA16816(d[mt][n2], a[mt], b[n2]);
        }

        if (c == 3) {
            const int n0c = nt * 128;
            const int cc0 = n0c + wn0 + (lane & 3) * 2;
            fp16* dst   = (n0c < 256) ? g_q : ((n0c < 512) ? g_k : g_v);
            int   cbase = (n0c < 256) ? 0   : ((n0c < 512) ? 256 : 512);
            const float scl = (n0c < 256) ? SCALEF : 1.0f;
            #pragma unroll
            for (int mt = 0; mt < 4; mt++) {
                int g0 = m0 + wm0 + mt * 16 + (lane >> 2);
                #pragma unroll
                for (int n2 = 0; n2 < 4; n2++) {
                    int col = cc0 + n2 * 8;
                    float bx = bias[col], by = bias[col + 1];
                    float v0 = (d[mt][n2][0] + bx) * scl, v1 = (d[mt][n2][1] + by) * scl;
                    float v2 = (d[mt][n2][2] + bx) * scl, v3 = (d[mt][n2][3] + by) * scl;
                    int cc  = col - cbase;
                    size_t hb = (size_t)(cc >> 5) * HPLANE + (cc & 31);
                    *(uint32_t*)(dst + hb + (size_t)g0 * 32)       = packh(v0, v1);
                    *(uint32_t*)(dst + hb + (size_t)(g0 + 8) * 32) = packh(v2, v3);
                    d[mt][n2][0] = 0.f; d[mt][n2][1] = 0.f;
                    d[mt][n2][2] = 0.f; d[mt][n2][3] = 0.f;
                }
            }
        }
        if (gc < 23) __syncthreads();
    }
}

// ---------------------------------------------------------------------------
// K2: tensor-core windowed attention, single fp16 everywhere.
// One block per (window, head), 4 warps, warp = 16 query rows.
// ---------------------------------------------------------------------------
__global__ __launch_bounds__(128) void attn_kernel(const float* __restrict__ pos_enc)
{
    __shared__ fp16 qh[64 * 40];
    __shared__ fp16 kh[64 * 40];
    __shared__ fp16 vh[32 * 72];               // transposed [dim][col]
    __shared__ float pe[225];
    __shared__ int   rg[64];

    const int w    = blockIdx.x;
    const int h    = blockIdx.y;
    const int tid  = threadIdx.x;
    const int lane = tid & 31;
    const int wp   = tid >> 5;

    const size_t hb = (size_t)h * HPLANE + (size_t)(w * 64) * 32;

    for (int t = tid; t < 256; t += 128) {
        int i = t >> 2, d0 = (t & 3) * 8;
        *(uint4*)(qh + i * 40 + d0) = *(const uint4*)(g_q + hb + i * 32 + d0);
    }
    for (int t = tid; t < 256; t += 128) {
        int i = t >> 2, d0 = (t & 3) * 8;
        *(uint4*)(kh + i * 40 + d0) = *(const uint4*)(g_k + hb + i * 32 + d0);
    }
    for (int t = tid; t < 256; t += 128) {
        int i = t >> 2, d0 = (t & 3) * 8;
        fp16 tmp[8];
        *(uint4*)tmp = *(const uint4*)(g_v + hb + i * 32 + d0);
        #pragma unroll
        for (int e = 0; e < 8; e++) vh[(d0 + e) * 72 + i] = tmp[e];
    }
    for (int idx = tid; idx < 225; idx += 128) pe[idx] = pos_enc[h * 225 + idx];
    if (tid < 64) {
        int wl = w & 63;
        int r  = ((wl >> 3) << 3) + (tid >> 3);
        int c  = ((wl & 7) << 3) + (tid & 7);
        int rr = (r < 56) ? 0 : ((r < 60) ? 1 : 2);
        int cc = (c < 56) ? 0 : ((c < 60) ? 1 : 2);
        rg[tid] = rr * 3 + cc;
    }
    __syncthreads();

    const uint32_t uqh = smem_u32(qh);
    const uint32_t ukh = smem_u32(kh);
    const uint32_t uvh = smem_u32(vh);

    // ---- S = q k^T ----
    float c[8][4];
    #pragma unroll
    for (int j = 0; j < 8; j++)
        #pragma unroll
        for (int q = 0; q < 4; q++) c[j][q] = 0.f;

    uint32_t aq[2][4];
    #pragma unroll
    for (int ks = 0; ks < 2; ks++) {
        uint32_t off = (uint32_t)((wp * 16 + (lane & 15)) * 80 +
                                  (ks * 16 + ((lane >> 1) & 8)) * 2);
        LDSM4(aq[ks], uqh + off);
    }
    #pragma unroll
    for (int np = 0; np < 4; np++) {
        #pragma unroll
        for (int ks = 0; ks < 2; ks++) {
            uint32_t off = (uint32_t)((np * 16 + (lane & 7) + ((lane & 16) ? 8 : 0)) * 80 +
                                      (ks * 16 + ((lane & 8) ? 8 : 0)) * 2);
            uint32_t bh[4];
            LDSM4(bh, ukh + off);
            MMA16816(c[2 * np],     aq[ks], &bh[0]);
            MMA16816(c[2 * np + 1], aq[ks], &bh[2]);
        }
    }

    // ---- bias + mask + softmax on fragments ----
    const int r0 = wp * 16 + (lane >> 2);
    const int r1 = r0 + 8;
    const int yi0 = r0 >> 3, xi0 = r0 & 7, ri0 = rg[r0];
    const int yi1 = r1 >> 3, xi1 = r1 & 7, ri1 = rg[r1];
    float mx0 = -INFINITY, mx1 = -INFINITY;
    #pragma unroll
    for (int j = 0; j < 8; j++) {
        #pragma unroll
        for (int dd = 0; dd < 2; dd++) {
            int col = j * 8 + (lane & 3) * 2 + dd;
            int yj = col >> 3, xj = col & 7;
            int rc = rg[col];
            c[j][dd]     = (rc == ri0)
                ? c[j][dd]     + pe[(yi0 - yj + 7) * 15 + (xi0 - xj + 7)] : -INFINITY;
            c[j][dd + 2] = (rc == ri1)
                ? c[j][dd + 2] + pe[(yi1 - yj + 7) * 15 + (xi1 - xj + 7)] : -INFINITY;
            mx0 = fmaxf(mx0, c[j][dd]);
            mx1 = fmaxf(mx1, c[j][dd + 2]);
        }
    }
    mx0 = fmaxf(mx0, __shfl_xor_sync(0xffffffffu, mx0, 1));
    mx0 = fmaxf(mx0, __shfl_xor_sync(0xffffffffu, mx0, 2));
    mx1 = fmaxf(mx1, __shfl_xor_sync(0xffffffffu, mx1, 1));
    mx1 = fmaxf(mx1, __shfl_xor_sync(0xffffffffu, mx1, 2));
    float s0 = 0.f, s1 = 0.f;
    #pragma unroll
    for (int j = 0; j < 8; j++) {
        #pragma unroll
        for (int dd = 0; dd < 2; dd++) {
            c[j][dd]     = __expf(c[j][dd] - mx0);     s0 += c[j][dd];
            c[j][dd + 2] = __expf(c[j][dd + 2] - mx1); s1 += c[j][dd + 2];
        }
    }
    s0 += __shfl_xor_sync(0xffffffffu, s0, 1);
    s0 += __shfl_xor_sync(0xffffffffu, s0, 2);
    s1 += __shfl_xor_sync(0xffffffffu, s1, 1);
    s1 += __shfl_xor_sync(0xffffffffu, s1, 2);
    const float inv0 = 1.0f / s0, inv1 = 1.0f / s1;

    // ---- repack P (C-frag -> A-frag), single fp16 ----
    uint32_t ph[4][4];
    #pragma unroll
    for (int t = 0; t < 4; t++) {
        #pragma unroll
        for (int q = 0; q < 4; q++) {
            int nt = 2 * t + (q >> 1);
            int p0 = (q & 1) * 2;
            float iv = (p0 == 0) ? inv0 : inv1;
            ph[t][q] = packh(c[nt][p0] * iv, c[nt][p0 + 1] * iv);
        }
    }

    // ---- O = P v ----
    float o[4][4];
    #pragma unroll
    for (int nt = 0; nt < 4; nt++)
        #pragma unroll
        for (int q = 0; q < 4; q++) o[nt][q] = 0.f;

    #pragma unroll
    for (int t = 0; t < 4; t++) {
        #pragma unroll
        for (int nb = 0; nb < 2; nb++) {
            uint32_t off = (uint32_t)((nb * 16 + (lane & 7) + ((lane & 16) ? 8 : 0)) * 144 +
                                      (t * 16 + ((lane & 8) ? 8 : 0)) * 2);
            uint32_t bh[4];
            LDSM4(bh, uvh + off);
            MMA16816(o[2 * nb],     ph[t], &bh[0]);
            MMA16816(o[2 * nb + 1], ph[t], &bh[2]);
        }
    }

    // ---- epilogue: fp16 to g_att2 (row-major [row][256]) ----
    size_t rb0 = (size_t)(w * 64 + r0) * 256 + h * 32;
    size_t rb1 = (size_t)(w * 64 + r1) * 256 + h * 32;
    #pragma unroll
    for (int nt = 0; nt < 4; nt++) {
        int d0 = nt * 8 + (lane & 3) * 2;
        *(uint32_t*)(g_att2 + rb0 + d0) = packh(o[nt][0], o[nt][1]);
        *(uint32_t*)(g_att2 + rb1 + d0) = packh(o[nt][2], o[nt][3]);
    }
}

// ---------------------------------------------------------------------------
// K3: single-pass-A out-projection GEMM.  grid = 1024 m-tiles; A (g_att2)
// staged once via cp.async (64KB), 2 n-tiles of w_out streamed (8 chunks);
// bias + inverse-roll scatter, f32 output.
// smem: A 65536 | B 2x16384  = 98304 B;  2 CTAs/SM.
// ---------------------------------------------------------------------------
__global__ __launch_bounds__(256, 2) void out_gemm(const float* __restrict__ bias,
                                                   float* __restrict__ Cout)
{
    extern __shared__ __align__(1024) char smem[];

    const int tid  = threadIdx.x;
    const int lane = tid & 31;
    const int warp = tid >> 5;
    const int m0   = blockIdx.x * 128;
    const uint32_t sbase = smem_u32(smem);
    const uint32_t bbase = sbase + 65536;

    // ---- stage A tile once (4 chunk-blocks of 16KB, SW128) ----
    #pragma unroll
    for (int kc = 0; kc < 4; kc++) {
        char* blk = smem + kc * 16384;
        uint32_t ub = smem_u32(blk);
        #pragma unroll
        for (int i = 0; i < 4; i++) {
            int idx = tid + i * 256;
            int r  = idx >> 3;
            int ch = idx & 7;
            uint32_t off = (uint32_t)(r * 128 + ch * 16);
            const fp16* as = g_att2 + (size_t)(m0 + r) * 256 + kc * 64 + ch * 8;
            asm volatile("cp.async.cg.shared.global [%0], [%1], 16;"
                         :: "r"(ub + SWZ(off)), "l"(as));
        }
    }
    asm volatile("cp.async.commit_group;");

    auto stageB = [&](int gc, int buf) {
        int nt  = gc >> 2;
        int kin = (gc & 3) * 64;
        uint32_t bb = bbase + buf * 16384;
        #pragma unroll
        for (int i = 0; i < 4; i++) {
            int idx = tid + i * 256;
            int r  = idx >> 3;
            int ch = idx & 7;
            uint32_t off = (uint32_t)(r * 128 + ch * 16);
            const fp16* bs = g_w3 + (size_t)(nt * 128 + r) * 256 + kin + ch * 8;
            asm volatile("cp.async.cg.shared.global [%0], [%1], 16;"
                         :: "r"(bb + SWZ(off)), "l"(bs));
        }
        asm volatile("cp.async.commit_group;");
    };

    float d[4][4][4];
    #pragma unroll
    for (int mt = 0; mt < 4; mt++)
        #pragma unroll
        for (int nt = 0; nt < 4; nt++)
            #pragma unroll
            for (int j = 0; j < 4; j++) d[mt][nt][j] = 0.f;

    const int wm0 = (warp >> 2) * 64;
    const int wn0 = (warp & 3) * 32;

    stageB(0, 0);
    #pragma unroll 1
    for (int gc = 0; gc < 8; gc++) {
        const int c  = gc & 3;
        const int nt = gc >> 2;
        if (gc < 7) {
            stageB(gc + 1, (gc + 1) & 1);
            asm volatile("cp.async.wait_group 1;");
        } else {
            asm volatile("cp.async.wait_group 0;");
        }
        __syncthreads();

        uint32_t ab = sbase + c * 16384;
        uint32_t bb = bbase + (gc & 1) * 16384;

        #pragma unroll
        for (int ks = 0; ks < 4; ks++) {
            uint32_t a[4][4], b[4][2];
            #pragma unroll
            for (int mt = 0; mt < 4; mt++) {
                int row = wm0 + mt * 16 + (lane & 15);
                int col = ks * 16 + ((lane >> 1) & 8);
                uint32_t off = (uint32_t)(row * 128 + col * 2);
                LDSM4(a[mt], ab + SWZ(off));
            }
            #pragma unroll
            for (int np = 0; np < 2; np++) {
                int row = wn0 + np * 16 + (lane & 7) + ((lane & 16) ? 8 : 0);
                int col = ks * 16 + ((lane & 8) ? 8 : 0);
                uint32_t off = (uint32_t)(row * 128 + col * 2);
                uint32_t t[4];
                LDSM4(t, bb + SWZ(off));
                b[2 * np][0] = t[0]; b[2 * np][1] = t[1];
                b[2 * np + 1][0] = t[2]; b[2 * np + 1][1] = t[3];
            }
            #pragma unroll
            for (int mt = 0; mt < 4; mt++)
                #pragma unroll
                for (int n2 = 0; n2 < 4; n2++)
                    MMA16816(d[mt][n2], a[mt], b[n2]);
        }

        if (c == 3) {
            // ---- epilogue for n-tile nt: bias + inverse-roll scatter ----
            const int n0c = nt * 128;
            const int cc0 = n0c + wn0 + (lane & 3) * 2;
            #pragma unroll
            for (int mt = 0; mt < 4; mt++) {
                int g0 = m0 + wm0 + mt * 16 + (lane >> 2);
                size_t ob0 = (size_t)gather_off(g0);
                size_t ob1 = (size_t)gather_off(g0 + 8);
                #pragma unroll
                for (int n2 = 0; n2 < 4; n2++) {
                    int col = cc0 + n2 * 8;
                    float bx = bias[col], by = bias[col + 1];
                    float2 o0 = {d[mt][n2][0] + bx, d[mt][n2][1] + by};
                    float2 o1 = {d[mt][n2][2] + bx, d[mt][n2][3] + by};
                    *(float2*)(Cout + ob0 + col) = o0;
                    *(float2*)(Cout + ob1 + col) = o1;
                    d[mt][n2][0] = 0.f; d[mt][n2][1] = 0.f;
                    d[mt][n2][2] = 0.f; d[mt][n2][3] = 0.f;
                }
            }
        }
        if (gc < 7) __syncthreads();
    }
}

// ---------------------------------------------------------------------------
extern "C" void kernel_launch(void* const* d_in, const int* in_sizes, int n_in,
                              void* d_out, int out_size)
{
    const float* x     = (const float*)d_in[0];
    const float* w_qkv = (const float*)d_in[1];
    const float* b_qkv = (const float*)d_in[2];
    const float* w_out = (const float*)d_in[3];
    const float* b_out = (const float*)d_in[4];
    const float* pos   = (const float*)d_in[5];
    float* out = (float*)d_out;

    const int SMEM1 = 98304;   // qkv_gemm: A 64KB + B 2x16KB
    const int SMEM3 = 98304;   // out_gemm: same layout
    cudaFuncSetAttribute(qkv_gemm,
                         cudaFuncAttributeMaxDynamicSharedMemorySize, SMEM1);
    cudaFuncSetAttribute(out_gemm,
                         cudaFuncAttributeMaxDynamicSharedMemorySize, SMEM3);

    convert_w<<<256, 256>>>(w_qkv, w_out);
    qkv_gemm<<<1024, 256, SMEM1>>>(x, b_qkv);
    attn_kernel<<<dim3(2048, 8), 128>>>(pos);
    out_gemm<<<1024, 256, SMEM3>>>(b_out, out);
}